// round 5
// baseline (speedup 1.0000x reference)
#include <cuda_runtime.h>
#include <cstdint>

// T = 2000 tags, V = 20000 videos, D = 768, E_POS = E_NEG = 100000
// Output layout: [cls_score (V*T f32), labels (V*T f32)], row index = video.

#define D_DIM    768
#define T_DIM    2000
#define V_DIM    20000
#define BIN_CAP  64       // edges/video ~ Poisson(10); P(>64) ~ 0

// ---------------------------------------------------------------------------
// Static device scratch. g_cursor starts zeroed (module load) and is reset to
// zero by fused_kernel every run, so each graph replay sees 0.
// ---------------------------------------------------------------------------
__device__ int      g_cursor[V_DIM];
__device__ unsigned g_edges [V_DIM * BIN_CAP];  // bit31 = isPos, low bits = tag

// ---------------------------------------------------------------------------
// Bin edges by VIDEO (dst) into fixed-capacity bins.
// ---------------------------------------------------------------------------
__global__ void scatter_kernel(const int* __restrict__ pos_src,
                               const int* __restrict__ pos_dst,
                               const int* __restrict__ neg_src,
                               const int* __restrict__ neg_dst,
                               int nPos, int nTot) {
    int i = blockIdx.x * blockDim.x + threadIdx.x;
    if (i < nTot) {
        int v; unsigned enc;
        if (i < nPos) { v = pos_dst[i];        enc = (unsigned)pos_src[i] | 0x80000000u; }
        else          { v = neg_dst[i - nPos]; enc = (unsigned)neg_src[i - nPos]; }
        int slot = atomicAdd(&g_cursor[v], 1);
        if (slot < BIN_CAP)
            g_edges[v * BIN_CAP + slot] = enc;
    }
}

// ---------------------------------------------------------------------------
// One block per video row:
//  1) zero a 16KB smem image of its cls row + labels row
//  2) stage the video feature row in registers
//  3) warp-per-edge: gather tag row (6MB table, L2-resident), dot, reduce,
//     smem atomicAdd into the row image
//  4) stream both complete rows to gmem with evict-first float4 stores
// Fuses the 320MB zero pass into the compute pass; no gmem atomics.
//
// RACE FIX vs R4: cursor is read by ONE thread, broadcast through shared
// memory, and reset by that same thread; the existing __syncthreads()
// publishes it before any warp uses n.
// ---------------------------------------------------------------------------
__global__ __launch_bounds__(256) void fused_kernel(
    const float* __restrict__ h_tag,
    const float* __restrict__ h_video,
    float*       __restrict__ cls,
    float*       __restrict__ labels)
{
    __shared__ float4 s_row[2 * T_DIM / 4];   // [0:500) cls, [500:1000) labels
    __shared__ int    s_n;

    const int v    = blockIdx.x;
    const int tid  = threadIdx.x;
    const int lane = tid & 31;
    const int warp = tid >> 5;

    // 1) zero the smem row image; single thread reads+resets cursor
    if (tid == 0) {
        int c = g_cursor[v];
        s_n = (c > BIN_CAP) ? BIN_CAP : c;
        g_cursor[v] = 0;                     // self-reset for next replay
    }
#pragma unroll
    for (int i = tid; i < 2 * T_DIM / 4; i += 256)
        s_row[i] = make_float4(0.f, 0.f, 0.f, 0.f);
    __syncthreads();

    const int n = s_n;

    if (n > 0) {
        // 2) stage video row in registers (per warp; L1 broadcasts across warps)
        const float4* b = reinterpret_cast<const float4*>(h_video + (size_t)v * D_DIM);
        float4 v0 = b[lane +   0];
        float4 v1 = b[lane +  32];
        float4 v2 = b[lane +  64];
        float4 v3 = b[lane +  96];
        float4 v4 = b[lane + 128];
        float4 v5 = b[lane + 160];

        float* s_cls = reinterpret_cast<float*>(s_row);
        float* s_lab = s_cls + T_DIM;
        const unsigned* elist = g_edges + (size_t)v * BIN_CAP;

        // 3) warp-per-edge gather + dot
        for (int e = warp; e < n; e += 8) {
            unsigned enc = elist[e];
            int t = (int)(enc & 0x7fffffffu);
            const float4* a = reinterpret_cast<const float4*>(h_tag + (size_t)t * D_DIM);

            float4 a0 = a[lane +   0];
            float4 a1 = a[lane +  32];
            float4 a2 = a[lane +  64];
            float4 a3 = a[lane +  96];
            float4 a4 = a[lane + 128];
            float4 a5 = a[lane + 160];

            float acc;
            acc  = a0.x * v0.x + a0.y * v0.y + a0.z * v0.z + a0.w * v0.w;
            acc += a1.x * v1.x + a1.y * v1.y + a1.z * v1.z + a1.w * v1.w;
            acc += a2.x * v2.x + a2.y * v2.y + a2.z * v2.z + a2.w * v2.w;
            acc += a3.x * v3.x + a3.y * v3.y + a3.z * v3.z + a3.w * v3.w;
            acc += a4.x * v4.x + a4.y * v4.y + a4.z * v4.z + a4.w * v4.w;
            acc += a5.x * v5.x + a5.y * v5.y + a5.z * v5.z + a5.w * v5.w;

#pragma unroll
            for (int off = 16; off > 0; off >>= 1)
                acc += __shfl_xor_sync(0xffffffffu, acc, off);

            if (lane == 0) {
                atomicAdd(&s_cls[t], acc);
                if (enc & 0x80000000u) atomicAdd(&s_lab[t], 1.0f);
            }
        }
    }
    __syncthreads();

    // 4) stream both rows out (evict-first: don't pollute L2's feature tables)
    float4* out_cls = reinterpret_cast<float4*>(cls    + (size_t)v * T_DIM);
    float4* out_lab = reinterpret_cast<float4*>(labels + (size_t)v * T_DIM);
#pragma unroll
    for (int i = tid; i < T_DIM / 4; i += 256) {
        __stcs(&out_cls[i], s_row[i]);
        __stcs(&out_lab[i], s_row[i + T_DIM / 4]);
    }
}

// ---------------------------------------------------------------------------
extern "C" void kernel_launch(void* const* d_in, const int* in_sizes, int n_in,
                              void* d_out, int out_size)
{
    const float* h_tag   = (const float*)d_in[0];
    const float* h_video = (const float*)d_in[1];
    const int*   pos_src = (const int*)d_in[2];
    const int*   pos_dst = (const int*)d_in[3];
    const int*   neg_src = (const int*)d_in[4];
    const int*   neg_dst = (const int*)d_in[5];

    const int nPos = in_sizes[2];
    const int nNeg = in_sizes[4];
    const int nTot = nPos + nNeg;

    float* cls    = (float*)d_out;
    long long vt  = (long long)out_size / 2;
    float* labels = cls + vt;

    // 1) bin edges by video
    scatter_kernel<<<(nTot + 255) / 256, 256>>>(pos_src, pos_dst, neg_src, neg_dst,
                                                nPos, nTot);

    // 2) fused: compute scores + write entire output (zeros included)
    fused_kernel<<<V_DIM, 256>>>(h_tag, h_video, cls, labels);
}

// round 7
// speedup vs baseline: 1.5864x; 1.5864x over previous
#include <cuda_runtime.h>
#include <cstdint>

// T = 2000 tags, V = 20000 videos, D = 768, E_POS = E_NEG = 100000
// Output layout: [cls_score (V*T f32), labels (V*T f32)]
//
// Structure (race-free overlap):
//   1) scatter_kernel : bin edges by tag (atomic cursors)
//   2) mega_kernel    : 8000 blocks, two roles
//        - ZERO role (3 of 4): stream 320MB of zeros, evict-first
//        - EDGE role (1 of 4): per-tag dot products -> g_score scratch
//        The two roles touch disjoint memory => no ordering hazard.
//   3) fold_kernel    : add ~200k per-edge scores + labels into the zeroed
//                       output (stream-ordered after mega), reset cursors.
// Cursor lifecycle per replay: 0 -> scatter fills -> mega READS ONLY ->
// fold reads + resets to 0.   (R6 bug: mega also reset them -> fold saw 0.)

#define D_DIM    768
#define T_DIM    2000
#define BIN_CAP  192      // edges/tag ~ Poisson(100); P(>192) ~ 1e-12

__device__ int      g_cursor[T_DIM];
__device__ unsigned g_edges [T_DIM * BIN_CAP];   // bit31 = isPos, low = dst
__device__ float    g_score [T_DIM * BIN_CAP];   // per-edge dot results

// ---------------------------------------------------------------------------
__global__ void scatter_kernel(const int* __restrict__ pos_src,
                               const int* __restrict__ pos_dst,
                               const int* __restrict__ neg_src,
                               const int* __restrict__ neg_dst,
                               int nPos, int nTot) {
    int i = blockIdx.x * blockDim.x + threadIdx.x;
    if (i < nTot) {
        int t; unsigned enc;
        if (i < nPos) { t = pos_src[i];        enc = (unsigned)pos_dst[i] | 0x80000000u; }
        else          { t = neg_src[i - nPos]; enc = (unsigned)neg_dst[i - nPos]; }
        int slot = atomicAdd(&g_cursor[t], 1);
        if (slot < BIN_CAP)
            g_edges[t * BIN_CAP + slot] = enc;
    }
}

// ---------------------------------------------------------------------------
__global__ __launch_bounds__(256) void mega_kernel(
    const float* __restrict__ h_tag,
    const float* __restrict__ h_video,
    float4*      __restrict__ out_vec,
    long long    nvec)
{
    const int bid = blockIdx.x;
    const int tid = threadIdx.x;

    if ((bid & 3) != 0) {
        // ---------------- ZERO role ----------------------------------------
        long long zid  = (long long)(bid >> 2) * 3 + (bid & 3) - 1;
        const long long stride = 6000LL * 256LL;
        const float4 z = make_float4(0.f, 0.f, 0.f, 0.f);
        for (long long i = zid * 256 + tid; i < nvec; i += stride)
            __stcs(&out_vec[i], z);
        return;
    }

    // ------------------- EDGE role: one tag per block ----------------------
    const int t = bid >> 2;
    __shared__ float4 stag[D_DIM / 4];
    __shared__ int    s_n;

    if (tid == 0) {
        int c = g_cursor[t];          // READ ONLY -- fold_kernel resets it
        s_n = (c > BIN_CAP) ? BIN_CAP : c;
    }
    if (tid < D_DIM / 4)
        stag[tid] = reinterpret_cast<const float4*>(h_tag + (size_t)t * D_DIM)[tid];
    __syncthreads();

    const int lane = tid & 31;
    const int warp = tid >> 5;

    // tag row -> registers
    float4 ta0 = stag[lane +   0];
    float4 ta1 = stag[lane +  32];
    float4 ta2 = stag[lane +  64];
    float4 ta3 = stag[lane +  96];
    float4 ta4 = stag[lane + 128];
    float4 ta5 = stag[lane + 160];

    const int n = s_n;
    const unsigned* elist = g_edges + (size_t)t * BIN_CAP;
    float*          slist = g_score + (size_t)t * BIN_CAP;

    int i = warp;
    if (i >= n) return;

    unsigned enc = elist[i];
    const float4* bp =
        reinterpret_cast<const float4*>(h_video + (size_t)(enc & 0x7fffffffu) * D_DIM);
    float4 v0 = bp[lane +   0];
    float4 v1 = bp[lane +  32];
    float4 v2 = bp[lane +  64];
    float4 v3 = bp[lane +  96];
    float4 v4 = bp[lane + 128];
    float4 v5 = bp[lane + 160];

    while (true) {
        const int inext = i + 8;               // 8 warps per block
        const bool more = inext < n;

        // prefetch next edge's video row during the reduce
        unsigned enc_n = 0;
        float4 w0, w1, w2, w3, w4, w5;
        if (more) {
            enc_n = elist[inext];
            const float4* bn =
                reinterpret_cast<const float4*>(h_video + (size_t)(enc_n & 0x7fffffffu) * D_DIM);
            w0 = bn[lane +   0];
            w1 = bn[lane +  32];
            w2 = bn[lane +  64];
            w3 = bn[lane +  96];
            w4 = bn[lane + 128];
            w5 = bn[lane + 160];
        }

        float acc;
        acc  = ta0.x * v0.x + ta0.y * v0.y + ta0.z * v0.z + ta0.w * v0.w;
        acc += ta1.x * v1.x + ta1.y * v1.y + ta1.z * v1.z + ta1.w * v1.w;
        acc += ta2.x * v2.x + ta2.y * v2.y + ta2.z * v2.z + ta2.w * v2.w;
        acc += ta3.x * v3.x + ta3.y * v3.y + ta3.z * v3.z + ta3.w * v3.w;
        acc += ta4.x * v4.x + ta4.y * v4.y + ta4.z * v4.z + ta4.w * v4.w;
        acc += ta5.x * v5.x + ta5.y * v5.y + ta5.z * v5.z + ta5.w * v5.w;

#pragma unroll
        for (int off = 16; off > 0; off >>= 1)
            acc += __shfl_xor_sync(0xffffffffu, acc, off);

        if (lane == 0) slist[i] = acc;

        if (!more) break;
        i = inext; enc = enc_n;
        v0 = w0; v1 = w1; v2 = w2; v3 = w3; v4 = w4; v5 = w5;
    }
}

// ---------------------------------------------------------------------------
// Fold ~200k per-edge scores + labels into the zeroed output; reset cursors.
// Target cells were just written by the zero stream -> L2-hot REDG (~3us).
// ---------------------------------------------------------------------------
__global__ void fold_kernel(float* __restrict__ cls,
                            float* __restrict__ labels)
{
    int t = blockIdx.x;
    __shared__ int s_n;
    if (threadIdx.x == 0) {
        int c = g_cursor[t];
        s_n = (c > BIN_CAP) ? BIN_CAP : c;
        g_cursor[t] = 0;                 // sole reset point (for next replay)
    }
    __syncthreads();
    int n = s_n;
    for (int i = threadIdx.x; i < n; i += blockDim.x) {
        unsigned enc = g_edges[t * BIN_CAP + i];
        float    sc  = g_score[t * BIN_CAP + i];
        size_t cell = (size_t)(enc & 0x7fffffffu) * T_DIM + (size_t)t;
        atomicAdd(&cls[cell], sc);
        if (enc & 0x80000000u) atomicAdd(&labels[cell], 1.0f);
    }
}

// ---------------------------------------------------------------------------
extern "C" void kernel_launch(void* const* d_in, const int* in_sizes, int n_in,
                              void* d_out, int out_size)
{
    const float* h_tag   = (const float*)d_in[0];
    const float* h_video = (const float*)d_in[1];
    const int*   pos_src = (const int*)d_in[2];
    const int*   pos_dst = (const int*)d_in[3];
    const int*   neg_src = (const int*)d_in[4];
    const int*   neg_dst = (const int*)d_in[5];

    const int nPos = in_sizes[2];
    const int nNeg = in_sizes[4];
    const int nTot = nPos + nNeg;

    float* cls    = (float*)d_out;
    long long vt  = (long long)out_size / 2;
    float* labels = cls + vt;

    // 1) bin edges by tag
    scatter_kernel<<<(nTot + 255) / 256, 256>>>(pos_src, pos_dst, neg_src, neg_dst,
                                                nPos, nTot);

    // 2) overlapped zero-stream + edge-gather (disjoint writes, no hazard)
    long long nvec = (long long)out_size / 4;
    mega_kernel<<<8000, 256>>>(h_tag, h_video, (float4*)d_out, nvec);

    // 3) fold scores into zeroed output, reset cursors
    fold_kernel<<<T_DIM, 128>>>(cls, labels);
}